// round 8
// baseline (speedup 1.0000x reference)
#include <cuda_runtime.h>
#include <math.h>

#define NCB   10
#define KCB   2048
#define DD    256
#define SEMD  256
#define W2VD  1024
#define BT    16384              // B*T tokens
#define ZQ_ELEMS (BT*DD)         // 4194304
#define CODES_OFF ZQ_ELEMS
#define VQ_OFF   (CODES_OFF + BT*NCB)
#define SEM_OFF  (VQ_OFF + 1)
#define ASTR  60                 // A smem row stride (56 slots + pad, 16B aligned)
#define BPAD  256                // B smem row stride (contiguous rows)
#define APAD  68                 // gemm kernels' A stride (unchanged)
#define NTHR  224                // 7 warps

// balanced tiling: 272 tiles x 56 tokens + 24 tiles x 48 tokens = 16384,
// grid = 296 = 2 x 148 SMs -> one wave at occupancy 2, max 112 tok/SM
#define N56   272
#define OFF48 (N56*56)           // 15232

// -------- device scratch (no runtime allocation allowed) --------
__device__ float g_zq1[ZQ_ELEMS];     // z_q of codebook 0 (semantic head input)
__device__ float g_H[BT*SEMD];        // semantic hidden
__device__ float g_Et[NCB*DD*KCB];    // E transposed per codebook: [cb][d][k]
__device__ float g_en[NCB*KCB];       // ||e_k||^2 per codebook
__device__ float g_vqp[NCB];          // per-codebook sum of (q-r)^2
__device__ float g_semsum;            // sum of (pred-target)^2

// packed fp32x2 FMA (sm_103a): two bitwise-exact IEEE fp32 FMAs per issue slot
__device__ __forceinline__ void fma2(unsigned long long& d,
                                     unsigned long long a, unsigned long long b) {
    asm("fma.rn.f32x2 %0, %1, %2, %0;" : "+l"(d) : "l"(a), "l"(b));
}
__device__ __forceinline__ unsigned long long dup2(float a) {
    unsigned long long r;
    asm("mov.b64 %0, {%1, %1};" : "=l"(r) : "f"(a));
    return r;
}
__device__ __forceinline__ void unpk(float& lo, float& hi, unsigned long long v) {
    asm("mov.b64 {%0, %1}, %2;" : "=f"(lo), "=f"(hi) : "l"(v));
}
__device__ __forceinline__ void cp16(void* smem_dst, const void* gsrc) {
    unsigned s = (unsigned)__cvta_generic_to_shared(smem_dst);
    asm volatile("cp.async.cg.shared.global [%0], [%1], 16;" :: "r"(s), "l"(gsrc));
}

// ---------------- E transpose: g_Et[cb][d][k] = E[cb][k][d] ----------------
__global__ void k_trans(const float* __restrict__ E) {
    __shared__ float tile[64][65];
    int kt = blockIdx.x, dt = blockIdx.y, cb = blockIdx.z;
    int tid = threadIdx.x;
    const float* Ein = E + (size_t)cb * KCB * DD;
    float* Eout = g_Et + (size_t)cb * DD * KCB;
    #pragma unroll
    for (int i = 0; i < 16; i++) {
        int idx = i * 256 + tid;
        int r = idx >> 6, c = idx & 63;
        tile[r][c] = Ein[(size_t)(kt * 64 + r) * DD + dt * 64 + c];
    }
    __syncthreads();
    #pragma unroll
    for (int i = 0; i < 16; i++) {
        int idx = i * 256 + tid;
        int r = idx >> 6, c = idx & 63;
        Eout[(size_t)(dt * 64 + r) * KCB + kt * 64 + c] = tile[c][r];
    }
}

// ---------------- codeword norms (summation order preserved) ----------------
__global__ void k_enorm(const float* __restrict__ E) {
    int w = (blockIdx.x * blockDim.x + threadIdx.x) >> 5;
    int lane = threadIdx.x & 31;
    if (w >= NCB * KCB) return;
    const float* e = E + (size_t)w * DD;
    float s = 0.f;
    #pragma unroll
    for (int k = 0; k < 8; k++) { float v = e[lane + 32 * k]; s += v * v; }
    #pragma unroll
    for (int off = 16; off; off >>= 1) s += __shfl_down_sync(0xffffffffu, s, off);
    if (!lane) g_en[w] = s;
}

// ---------------- init: zero loss accumulators only ----------------
__global__ void k_init() {
    int i = threadIdx.x;
    if (i < NCB) g_vqp[i] = 0.f;
    if (i == NCB) g_semsum = 0.f;
}

// ---------------- fully fused RVQ body; NW active warps x 8 tokens ----------------
template<int NW>
__device__ __forceinline__ void rvq_body(
    int m0, const float* __restrict__ z, const float* __restrict__ E,
    float* __restrict__ out, float* sm, int tid, int lane, int wy)
{
    float* Asm = sm;                        // [256 d][ASTR] residual (token minor)
    float* Bs  = sm + 256 * ASTR;           // 2 x [16 d][BPAD]
    float* xxs = Bs + 2 * 16 * BPAD;        // [56]
    float* ens = xxs + 64;                  // [2048]

    const int mt = NW * 8;                  // tokens in this tile
    const bool act = (wy < NW);

    // load A tile from z into Asm[d][slot] (slot == local token, contiguous)
    const float4* Ag = reinterpret_cast<const float4*>(z + (size_t)m0 * DD);
    for (int f = tid; f < mt * 64; f += NTHR) {
        int tok = f >> 6, seg = f & 63;
        float4 v = Ag[f];
        int db = seg * 4;
        Asm[(db + 0) * ASTR + tok] = v.x;
        Asm[(db + 1) * ASTR + tok] = v.y;
        Asm[(db + 2) * ASTR + tok] = v.z;
        Asm[(db + 3) * ASTR + tok] = v.w;
    }

    // initial ||x||^2 per token (ascending j, shfl_down tree)
    if (act) {
        #pragma unroll
        for (int r = 0; r < 8; r++) {
            int tok = m0 + wy * 8 + r;
            const float* row = z + (size_t)tok * DD;
            float s = 0.f;
            #pragma unroll
            for (int k = 0; k < 8; k++) { float v = row[lane + 32 * k]; s += v * v; }
            #pragma unroll
            for (int off = 16; off; off >>= 1) s += __shfl_down_sync(0xffffffffu, s, off);
            if (!lane) xxs[wy * 8 + r] = s;
        }
    }

    for (int cb = 0; cb < NCB; cb++) {
        const float* Et  = g_Et + (size_t)cb * DD * KCB;
        const float* Ecb = E + (size_t)cb * KCB * DD;

        auto issueB = [&](int cc, float* buf) {
            int nt = cc >> 4, dc = cc & 15;
            #pragma unroll 5
            for (int i = tid; i < 1024; i += NTHR) {
                int row = i >> 6, col = (i & 63) * 4;
                cp16(&buf[row * BPAD + col],
                     Et + (size_t)(dc * 16 + row) * KCB + nt * 256 + col);
            }
            asm volatile("cp.async.commit_group;");
        };

        issueB(0, Bs);                      // chunk 0 in flight

        // stage codeword norms into smem
        {
            const float4* en4 = reinterpret_cast<const float4*>(g_en + cb * KCB);
            for (int k = tid; k < 512; k += NTHR)
                *reinterpret_cast<float4*>(&ens[k * 4]) = en4[k];
        }

        float mv[8]; int mi[8];
        #pragma unroll
        for (int r = 0; r < 8; r++) { mv[r] = INFINITY; mi[r] = 0; }
        unsigned long long acc[8][4];
        #pragma unroll
        for (int r = 0; r < 8; r++)
            #pragma unroll
            for (int q = 0; q < 4; q++) acc[r][q] = 0ull;

        for (int cc = 0; cc < 128; cc++) {             // 8 n-tiles * 16 d-chunks
            asm volatile("cp.async.wait_group 0;");
            __syncthreads();
            if (cc + 1 < 128) issueB(cc + 1, Bs + ((cc + 1) & 1) * 16 * BPAD);

            if (act) {
                const float* Bp = Bs + (cc & 1) * 16 * BPAD;
                int dbase = (cc & 15) * 16;

                // preload kk=0 operands
                ulonglong2 bb0 = *reinterpret_cast<const ulonglong2*>(
                    reinterpret_cast<const unsigned long long*>(&Bp[0]) + lane * 2);
                ulonglong2 bb1 = *reinterpret_cast<const ulonglong2*>(
                    reinterpret_cast<const unsigned long long*>(&Bp[0]) + 64 + lane * 2);
                float4 av0 = *reinterpret_cast<const float4*>(&Asm[dbase * ASTR + wy * 8]);
                float4 av1 = *reinterpret_cast<const float4*>(&Asm[dbase * ASTR + wy * 8 + 4]);

                #pragma unroll
                for (int kk = 0; kk < 16; kk++) {
                    ulonglong2 nb0, nb1; float4 nav0, nav1;
                    if (kk < 15) {                      // prefetch kk+1 operands
                        const unsigned long long* brn =
                            reinterpret_cast<const unsigned long long*>(&Bp[(kk + 1) * BPAD]);
                        nb0 = *reinterpret_cast<const ulonglong2*>(brn + lane * 2);
                        nb1 = *reinterpret_cast<const ulonglong2*>(brn + 64 + lane * 2);
                        nav0 = *reinterpret_cast<const float4*>(&Asm[(dbase + kk + 1) * ASTR + wy * 8]);
                        nav1 = *reinterpret_cast<const float4*>(&Asm[(dbase + kk + 1) * ASTR + wy * 8 + 4]);
                    }
                    float a[8] = {av0.x, av0.y, av0.z, av0.w, av1.x, av1.y, av1.z, av1.w};
                    #pragma unroll
                    for (int r = 0; r < 8; r++) {
                        unsigned long long a2 = dup2(a[r]);
                        fma2(acc[r][0], a2, bb0.x);
                        fma2(acc[r][1], a2, bb0.y);
                        fma2(acc[r][2], a2, bb1.x);
                        fma2(acc[r][3], a2, bb1.y);
                    }
                    if (kk < 15) { bb0 = nb0; bb1 = nb1; av0 = nav0; av1 = nav1; }
                }

                if ((cc & 15) == 15) {                 // n-tile argmin epilogue
                    int n0 = (cc >> 4) * 256;
                    float2 e01[4];
                    #pragma unroll
                    for (int q = 0; q < 4; q++) {
                        int kb = n0 + (q >> 1) * 128 + lane * 4 + (q & 1) * 2;
                        e01[q] = *reinterpret_cast<const float2*>(&ens[kb]);
                    }
                    #pragma unroll
                    for (int r = 0; r < 8; r++) {
                        float xr = xxs[wy * 8 + r];
                        #pragma unroll
                        for (int q = 0; q < 4; q++) {
                            int kb = n0 + (q >> 1) * 128 + lane * 4 + (q & 1) * 2;
                            float lo, hi;
                            unpk(lo, hi, acc[r][q]);
                            float s0 = (xr - 2.0f * lo) + e01[q].x;
                            float s1 = (xr - 2.0f * hi) + e01[q].y;
                            if (s0 < mv[r]) { mv[r] = s0; mi[r] = kb; }
                            if (s1 < mv[r]) { mv[r] = s1; mi[r] = kb + 1; }
                            acc[r][q] = 0ull;
                        }
                    }
                }
            }
        }

        if (act) {
            // argmin reduce across 32 lanes (first-index tie break)
            #pragma unroll
            for (int off = 1; off < 32; off <<= 1) {
                #pragma unroll
                for (int r = 0; r < 8; r++) {
                    float ov = __shfl_xor_sync(0xffffffffu, mv[r], off);
                    int   oi = __shfl_xor_sync(0xffffffffu, mi[r], off);
                    if (ov < mv[r] || (ov == mv[r] && oi < mi[r])) { mv[r] = ov; mi[r] = oi; }
                }
            }

            // fused straight-through update, residual updated IN SMEM
            float sl = 0.f;
            #pragma unroll
            for (int r = 0; r < 8; r++) {
                int slot = wy * 8 + r;
                int tok = m0 + slot;
                int idx = mi[r];
                const float* qrow = Ecb + (size_t)idx * DD;
                float* orow = out + (size_t)tok * DD;
                float* zrow = g_zq1 + (size_t)tok * DD;
                float sx = 0.f;
                #pragma unroll
                for (int j = 0; j < 8; j++) {
                    int d = lane + 32 * j;
                    float rr = Asm[d * ASTR + slot];
                    float q  = __ldg(&qrow[d]);
                    float df = q - rr;                 // fl(q - r)
                    float zq = rr + df;                // straight-through, jax order
                    float nr = rr - zq;                // new residual
                    if (cb == 0) { orow[d] = zq; zrow[d] = zq; }  // fl(0+zq)==zq
                    else orow[d] += zq;                // z_q_total accumulation
                    Asm[d * ASTR + slot] = nr;
                    sl += df * df;
                    sx += nr * nr;
                }
                #pragma unroll
                for (int off = 16; off; off >>= 1) sx += __shfl_down_sync(0xffffffffu, sx, off);
                if (lane == 0) {
                    xxs[slot] = sx;
                    out[CODES_OFF + tok * NCB + cb] = (float)idx;
                }
            }
            #pragma unroll
            for (int off = 16; off; off >>= 1) sl += __shfl_xor_sync(0xffffffffu, sl, off);
            if (lane == 0) atomicAdd(&g_vqp[cb], sl);
        }

        __syncthreads();   // ens/Bs WAR before next codebook restages them
    }
}

__global__ void __launch_bounds__(NTHR, 2)
k_rvq(const float* __restrict__ z, const float* __restrict__ E, float* __restrict__ out) {
    extern __shared__ float sm[];
    int tid = threadIdx.x;
    int lane = tid & 31, wy = tid >> 5;
    int b = blockIdx.x;
    if (b < N56) rvq_body<7>(b * 56, z, E, out, sm, tid, lane, wy);
    else         rvq_body<6>(OFF48 + (b - N56) * 48, z, E, out, sm, tid, lane, wy);
}

// ---------------- semantic head GEMM1: H = gelu(zq1 @ W1 + b1) ----------------
__global__ void __launch_bounds__(256, 2)
k_gemm1(const float* __restrict__ W1, const float* __restrict__ b1) {
    extern __shared__ float sm[];
    float* Asm = sm;                  // [256][APAD]
    float* Bs  = sm + 256 * APAD;     // [16][APAD]
    int tid = threadIdx.x, tx = tid & 15, ty = tid >> 4;
    int m0 = blockIdx.x * 64, n0 = blockIdx.y * 64;

    const float4* Ag = reinterpret_cast<const float4*>(g_zq1 + (size_t)m0 * DD);
    #pragma unroll
    for (int i = 0; i < 16; i++) {
        int f = tid + 256 * i;
        int tok = f >> 6, seg = f & 63;
        float4 v = Ag[tok * 64 + seg];
        int db = seg * 4;
        Asm[(db + 0) * APAD + tok] = v.x;
        Asm[(db + 1) * APAD + tok] = v.y;
        Asm[(db + 2) * APAD + tok] = v.z;
        Asm[(db + 3) * APAD + tok] = v.w;
    }
    __syncthreads();

    unsigned long long acc[4][2];
    #pragma unroll
    for (int r = 0; r < 4; r++) { acc[r][0] = 0ull; acc[r][1] = 0ull; }

    for (int dc = 0; dc < 16; dc++) {
        int dk = tid >> 4, nseg = tid & 15;
        float4 v = *reinterpret_cast<const float4*>(&W1[(size_t)(dc * 16 + dk) * SEMD + n0 + nseg * 4]);
        *reinterpret_cast<float4*>(&Bs[dk * APAD + nseg * 4]) = v;
        __syncthreads();
        #pragma unroll
        for (int kk = 0; kk < 16; kk++) {
            float4 av = *reinterpret_cast<const float4*>(&Asm[(dc * 16 + kk) * APAD + ty * 4]);
            ulonglong2 bb = *reinterpret_cast<const ulonglong2*>(&Bs[kk * APAD + tx * 4]);
            float a[4] = {av.x, av.y, av.z, av.w};
            #pragma unroll
            for (int r = 0; r < 4; r++) {
                unsigned long long a2 = dup2(a[r]);
                fma2(acc[r][0], a2, bb.x);
                fma2(acc[r][1], a2, bb.y);
            }
        }
        __syncthreads();
    }
    #pragma unroll
    for (int r = 0; r < 4; r++)
        #pragma unroll
        for (int q = 0; q < 2; q++) {
            int m = m0 + ty * 4 + r, n = n0 + tx * 4 + q * 2;
            float lo, hi;
            unpk(lo, hi, acc[r][q]);
            float x0 = lo + __ldg(&b1[n]);
            float x1 = hi + __ldg(&b1[n + 1]);
            g_H[(size_t)m * SEMD + n]     = 0.5f * x0 * (1.0f + erff(x0 * 0.70710678118654752f));
            g_H[(size_t)m * SEMD + n + 1] = 0.5f * x1 * (1.0f + erff(x1 * 0.70710678118654752f));
        }
}

// ---------------- semantic head GEMM2 + fused MSE reduction ----------------
__global__ void __launch_bounds__(256, 2)
k_gemm2(const float* __restrict__ W2, const float* __restrict__ b2, const float* __restrict__ tgt) {
    extern __shared__ float sm[];
    float* Asm = sm;
    float* Bs  = sm + 256 * APAD;
    int tid = threadIdx.x, tx = tid & 15, ty = tid >> 4;
    int m0 = blockIdx.x * 64, n0 = blockIdx.y * 64;

    const float4* Ag = reinterpret_cast<const float4*>(g_H + (size_t)m0 * SEMD);
    #pragma unroll
    for (int i = 0; i < 16; i++) {
        int f = tid + 256 * i;
        int tok = f >> 6, seg = f & 63;
        float4 v = Ag[tok * 64 + seg];
        int db = seg * 4;
        Asm[(db + 0) * APAD + tok] = v.x;
        Asm[(db + 1) * APAD + tok] = v.y;
        Asm[(db + 2) * APAD + tok] = v.z;
        Asm[(db + 3) * APAD + tok] = v.w;
    }
    __syncthreads();

    unsigned long long acc[4][2];
    #pragma unroll
    for (int r = 0; r < 4; r++) { acc[r][0] = 0ull; acc[r][1] = 0ull; }

    for (int dc = 0; dc < 16; dc++) {
        int dk = tid >> 4, nseg = tid & 15;
        float4 v = *reinterpret_cast<const float4*>(&W2[(size_t)(dc * 16 + dk) * W2VD + n0 + nseg * 4]);
        *reinterpret_cast<float4*>(&Bs[dk * APAD + nseg * 4]) = v;
        __syncthreads();
        #pragma unroll
        for (int kk = 0; kk < 16; kk++) {
            float4 av = *reinterpret_cast<const float4*>(&Asm[(dc * 16 + kk) * APAD + ty * 4]);
            ulonglong2 bb = *reinterpret_cast<const ulonglong2*>(&Bs[kk * APAD + tx * 4]);
            float a[4] = {av.x, av.y, av.z, av.w};
            #pragma unroll
            for (int r = 0; r < 4; r++) {
                unsigned long long a2 = dup2(a[r]);
                fma2(acc[r][0], a2, bb.x);
                fma2(acc[r][1], a2, bb.y);
            }
        }
        __syncthreads();
    }

    float ls = 0.f;
    #pragma unroll
    for (int r = 0; r < 4; r++)
        #pragma unroll
        for (int q = 0; q < 2; q++) {
            int m = m0 + ty * 4 + r, n = n0 + tx * 4 + q * 2;
            float lo, hi;
            unpk(lo, hi, acc[r][q]);
            float p0 = lo + __ldg(&b2[n]);
            float p1 = hi + __ldg(&b2[n + 1]);
            float d0 = p0 - __ldg(&tgt[(size_t)m * W2VD + n]);
            float d1 = p1 - __ldg(&tgt[(size_t)m * W2VD + n + 1]);
            ls += d0 * d0;
            ls += d1 * d1;
        }
    __shared__ float red[8];
    int lane = tid & 31, w = tid >> 5;
    #pragma unroll
    for (int off = 16; off; off >>= 1) ls += __shfl_xor_sync(0xffffffffu, ls, off);
    if (!lane) red[w] = ls;
    __syncthreads();
    if (tid < 8) {
        float t = red[tid];
        #pragma unroll
        for (int off = 4; off; off >>= 1) t += __shfl_xor_sync(0xffu, t, off);
        if (tid == 0) atomicAdd(&g_semsum, t);
    }
}

// ---------------- finalize scalars ----------------
__global__ void k_fin(float* __restrict__ out) {
    if (threadIdx.x == 0) {
        float vq = 0.f;
        #pragma unroll
        for (int i = 0; i < NCB; i++) {
            float m = g_vqp[i] * (1.0f / 4194304.0f);   // mean over B*T*D
            vq += m + 0.25f * m;                         // embedding + COMMIT*commitment
        }
        out[VQ_OFF] = vq;
        out[SEM_OFF] = g_semsum * (1.0f / 16777216.0f);  // mean over B*T*W2V
    }
}

// ---------------- launch ----------------
extern "C" void kernel_launch(void* const* d_in, const int* in_sizes, int n_in,
                              void* d_out, int out_size) {
    const float* z   = (const float*)d_in[0];
    const float* w2v = (const float*)d_in[1];
    const float* E   = (const float*)d_in[2];
    const float* W1  = (const float*)d_in[3];
    const float* b1  = (const float*)d_in[4];
    const float* W2  = (const float*)d_in[5];
    const float* b2  = (const float*)d_in[6];
    float* out = (float*)d_out;

    const int ARG_SMEM  = (256 * ASTR + 2 * 16 * BPAD + 64 + KCB) * 4;  // 102,656 B
    const int GEMM_SMEM = (256 * APAD + 16 * APAD) * 4;                 // 73,984 B
    cudaFuncSetAttribute(k_rvq,   cudaFuncAttributeMaxDynamicSharedMemorySize, ARG_SMEM);
    cudaFuncSetAttribute(k_gemm1, cudaFuncAttributeMaxDynamicSharedMemorySize, GEMM_SMEM);
    cudaFuncSetAttribute(k_gemm2, cudaFuncAttributeMaxDynamicSharedMemorySize, GEMM_SMEM);

    k_trans<<<dim3(KCB / 64, DD / 64, NCB), 256>>>(E);
    k_enorm<<<(NCB * KCB * 32 + 255) / 256, 256>>>(E);
    k_init<<<1, 32>>>();

    k_rvq<<<296, NTHR, ARG_SMEM>>>(z, E, out);

    k_gemm1<<<dim3(BT / 64, SEMD / 64), 256, GEMM_SMEM>>>(W1, b1);
    k_gemm2<<<dim3(BT / 64, W2VD / 64), 256, GEMM_SMEM>>>(W2, b2, w2v);
    k_fin<<<1, 32>>>(out);
}